// round 14
// baseline (speedup 1.0000x reference)
#include <cuda_runtime.h>
#include <cuda_bf16.h>
#include <mma.h>
#include <math.h>
#include <cstdint>
#include <cstddef>

#define HIDDEN 3584
#define NH 28
#define NKV 4
#define HD 128
#define NREP 7
#define BATCH 2
#define SEQ 2048
#define M_TOK (BATCH*SEQ)   // 4096
#define QDIM (NH*HD)        // 3584
#define KVDIM (NKV*HD)      // 512
#define NDIMC (QDIM + 2*KVDIM)   // 4608

typedef __nv_bfloat16 bf16;

// ---------------------------------------------------------------------------
// Scratch
// ---------------------------------------------------------------------------
__device__ __align__(128) bf16 g_hsh[(size_t)M_TOK*HIDDEN];
__device__ __align__(128) bf16 g_hsl[(size_t)M_TOK*HIDDEN];
__device__ __align__(128) bf16 g_Wch[(size_t)NDIMC*HIDDEN];
__device__ __align__(128) bf16 g_Wcl[(size_t)NDIMC*HIDDEN];
__device__ __align__(128) bf16 g_Woh[(size_t)HIDDEN*QDIM];
__device__ __align__(128) bf16 g_Wol[(size_t)HIDDEN*QDIM];

__device__ __align__(128) bf16 g_Qh[(size_t)M_TOK*QDIM];   // [B][NH][S][D]
__device__ __align__(128) bf16 g_Ql[(size_t)M_TOK*QDIM];
__device__ __align__(128) bf16 g_Kh[(size_t)M_TOK*KVDIM];  // [B][NKV][S][D]
__device__ __align__(128) bf16 g_Kl[(size_t)M_TOK*KVDIM];
__device__ __align__(128) bf16 g_Vh[(size_t)M_TOK*KVDIM];
__device__ __align__(128) bf16 g_Vl[(size_t)M_TOK*KVDIM];
__device__ __align__(128) bf16 g_Ah[(size_t)M_TOK*QDIM];
__device__ __align__(128) bf16 g_Al[(size_t)M_TOK*QDIM];

// ---------------------------------------------------------------------------
// helpers
// ---------------------------------------------------------------------------
__device__ __forceinline__ void bf16_split(float x, bf16& hi, bf16& lo) {
    hi = __float2bfloat16(x);
    lo = __float2bfloat16(x - __bfloat162float(hi));
}
__device__ __forceinline__ uint32_t smem_u32(const void* p) {
    return (uint32_t)__cvta_generic_to_shared(p);
}
__device__ __forceinline__ void cp_async16_sm(uint32_t s, const void* g) {
    asm volatile("cp.async.cg.shared.global [%0], [%1], 16;\n"
                 :: "r"(s), "l"(g));
}
__device__ __forceinline__ void ldsm_x4(uint32_t r[4], uint32_t addr) {
    asm volatile("ldmatrix.sync.aligned.m8n8.x4.shared.b16 {%0,%1,%2,%3}, [%4];"
        : "=r"(r[0]), "=r"(r[1]), "=r"(r[2]), "=r"(r[3]) : "r"(addr));
}
__device__ __forceinline__ void ldsm_x4t(uint32_t r[4], uint32_t addr) {
    asm volatile("ldmatrix.sync.aligned.m8n8.x4.trans.shared.b16 {%0,%1,%2,%3}, [%4];"
        : "=r"(r[0]), "=r"(r[1]), "=r"(r[2]), "=r"(r[3]) : "r"(addr));
}
__device__ __forceinline__ void mma16816(float d[4], const uint32_t a[4],
                                         const uint32_t b[2]) {
    asm volatile(
        "mma.sync.aligned.m16n8k16.row.col.f32.bf16.bf16.f32 "
        "{%0,%1,%2,%3}, {%4,%5,%6,%7}, {%8,%9}, {%0,%1,%2,%3};"
        : "+f"(d[0]), "+f"(d[1]), "+f"(d[2]), "+f"(d[3])
        : "r"(a[0]), "r"(a[1]), "r"(a[2]), "r"(a[3]), "r"(b[0]), "r"(b[1]));
}
__device__ __forceinline__ uint32_t pack2(bf16 a, bf16 b) {
    __nv_bfloat162 v(a, b);
    return *(uint32_t*)&v;
}

// ---------------------------------------------------------------------------
// fused split kernel: all 5 tensors in one launch
// ---------------------------------------------------------------------------
#define SP_N0 ((size_t)M_TOK*HIDDEN/4)                 // hs
#define SP_N1 (SP_N0 + (size_t)QDIM*HIDDEN/4)          // Wq
#define SP_N2 (SP_N1 + (size_t)KVDIM*HIDDEN/4)         // Wk
#define SP_N3 (SP_N2 + (size_t)KVDIM*HIDDEN/4)         // Wv
#define SP_N4 (SP_N3 + (size_t)HIDDEN*QDIM/4)          // Wo
#define SP_GRID ((unsigned)((SP_N4 + 255) / 256))

__global__ void __launch_bounds__(256) split_all(
    const float4* __restrict__ hs, const float4* __restrict__ Wq,
    const float4* __restrict__ Wk, const float4* __restrict__ Wv,
    const float4* __restrict__ Wo)
{
    size_t i = (size_t)blockIdx.x*256 + threadIdx.x;
    if (i >= SP_N4) return;
    const float4* src;
    bf16 *hi, *lo;
    size_t j;
    if (i < SP_N0)      { j = i;         src = hs; hi = g_hsh; lo = g_hsl; }
    else if (i < SP_N1) { j = i - SP_N0; src = Wq; hi = g_Wch; lo = g_Wcl; }
    else if (i < SP_N2) { j = i - SP_N1; src = Wk;
                          hi = g_Wch + (size_t)QDIM*HIDDEN;
                          lo = g_Wcl + (size_t)QDIM*HIDDEN; }
    else if (i < SP_N3) { j = i - SP_N2; src = Wv;
                          hi = g_Wch + (size_t)(QDIM+KVDIM)*HIDDEN;
                          lo = g_Wcl + (size_t)(QDIM+KVDIM)*HIDDEN; }
    else                { j = i - SP_N3; src = Wo; hi = g_Woh; lo = g_Wol; }
    float4 v = src[j];
    bf16 hx, lx, hy, ly, hz, lz, hw, lw;
    bf16_split(v.x, hx, lx);
    bf16_split(v.y, hy, ly);
    bf16_split(v.z, hz, lz);
    bf16_split(v.w, hw, lw);
    __nv_bfloat162* h2 = (__nv_bfloat162*)hi;
    __nv_bfloat162* l2 = (__nv_bfloat162*)lo;
    h2[2*j]   = __nv_bfloat162(hx, hy);
    h2[2*j+1] = __nv_bfloat162(hz, hw);
    l2[2*j]   = __nv_bfloat162(lx, ly);
    l2[2*j+1] = __nv_bfloat162(lz, lw);
}

// zero fp32 output (in-graph; out is re-poisoned each replay)
__global__ void __launch_bounds__(256) zero_out(float4* __restrict__ p, size_t n4)
{
    size_t i = (size_t)blockIdx.x*256 + threadIdx.x;
    if (i < n4) p[i] = make_float4(0.f, 0.f, 0.f, 0.f);
}

// ===========================================================================
// Shared GEMM mainloop config: BM=256 BN=128 BK=64, 8 warps, 64x64 warp tile
// ===========================================================================
#define BM3 256
#define BN3 128
#define BK3 64
#define LDT3 72
#define OFF3_AH 0
#define OFF3_AL (BM3*LDT3)
#define OFF3_BH (2*BM3*LDT3)
#define OFF3_BL (2*BM3*LDT3 + BN3*LDT3)
#define STAGE3_HALFS (2*BM3*LDT3 + 2*BN3*LDT3)   // 55296
#define SMEM3_BYTES (2*STAGE3_HALFS*2)           // 221184
#define LDSC 132                                 // fp32 C-tile stride (epilogue)

// mainloop macro (accumulates into acc[4][8][4]); Kbase allows split-K
#define GEMM_MAINLOOP(Ahp, Alp, Whp, Wlp, Kstride, Tchunks, Kbase)             \
    auto load_chunk = [&](int chunk, int slot) {                               \
        const int k0 = (Kbase) + chunk * BK3;                                  \
        const uint32_t base = smb + (uint32_t)(slot*STAGE3_HALFS*2);           \
        _Pragma("unroll")                                                      \
        for (int it = 0; it < 24; it++) {                                      \
            int c = tid + it*256;                                              \
            const bf16* g;                                                     \
            uint32_t soff;                                                     \
            if (c < 4096) {                                                    \
                int t = c >> 11, idx = c & 2047;                               \
                int row = idx >> 3, c16 = idx & 7;                             \
                g = (t ? Alp : Ahp) + (size_t)(bm+row)*(Kstride) + k0 + c16*8; \
                soff = (uint32_t)(((t ? OFF3_AL : OFF3_AH) + row*LDT3 + c16*8) * 2); \
            } else {                                                           \
                int d = c - 4096;                                              \
                int t = d >> 10, idx = d & 1023;                               \
                int row = idx >> 3, c16 = idx & 7;                             \
                g = (t ? Wlp : Whp) + (size_t)(bn+row)*(Kstride) + k0 + c16*8; \
                soff = (uint32_t)(((t ? OFF3_BL : OFF3_BH) + row*LDT3 + c16*8) * 2); \
            }                                                                  \
            cp_async16_sm(base + soff, g);                                     \
        }                                                                      \
        asm volatile("cp.async.commit_group;" ::: "memory");                   \
    };                                                                         \
    const int arow  = wr*64 + (lane & 7) + ((lane >> 3) & 1)*8;                \
    const int acol8 = ((lane >> 4) & 1)*8;                                     \
    const int brow  = wc*64 + (lane & 7) + ((lane >> 4) & 1)*8;                \
    const int bcol8 = ((lane >> 3) & 1)*8;                                     \
    const int T = (Tchunks);                                                   \
    load_chunk(0, 0);                                                          \
    for (int i = 0; i < T; i++) {                                              \
        const int slot = i & 1;                                                \
        asm volatile("cp.async.wait_group 0;" ::: "memory");                   \
        __syncthreads();                                                       \
        if (i + 1 < T) load_chunk(i + 1, slot ^ 1);                            \
        const uint32_t st = smb + (uint32_t)(slot*STAGE3_HALFS*2);             \
        const uint32_t sAh = st + OFF3_AH*2;                                   \
        const uint32_t sAl = st + OFF3_AL*2;                                   \
        const uint32_t sBh = st + OFF3_BH*2;                                   \
        const uint32_t sBl = st + OFF3_BL*2;                                   \
        _Pragma("unroll")                                                      \
        for (int ks = 0; ks < 4; ks++) {                                       \
            const int kofs = ks*16;                                            \
            uint32_t ah[4][4], al[4][4];                                       \
            _Pragma("unroll")                                                  \
            for (int mi = 0; mi < 4; mi++) {                                   \
                uint32_t ao = (uint32_t)(((arow + mi*16)*LDT3 + kofs + acol8)*2); \
                ldsm_x4(ah[mi], sAh + ao);                                     \
                ldsm_x4(al[mi], sAl + ao);                                     \
            }                                                                  \
            uint32_t bh[2][4], bl[2][4];                                       \
            {                                                                  \
                uint32_t bo = (uint32_t)((brow*LDT3 + kofs + bcol8)*2);        \
                ldsm_x4(bh[0], sBh + bo);                                      \
                ldsm_x4(bl[0], sBl + bo);                                      \
            }                                                                  \
            _Pragma("unroll")                                                  \
            for (int np = 0; np < 4; np++) {                                   \
                const int cur = np & 1;                                        \
                if (np < 3) {                                                  \
                    uint32_t bo = (uint32_t)(((brow + (np+1)*16)*LDT3 + kofs + bcol8)*2); \
                    ldsm_x4(bh[cur ^ 1], sBh + bo);                            \
                    ldsm_x4(bl[cur ^ 1], sBl + bo);                            \
                }                                                              \
                _Pragma("unroll")                                              \
                for (int mi = 0; mi < 4; mi++) {                               \
                    mma16816(acc[mi][2*np],   al[mi], &bh[cur][0]);            \
                    mma16816(acc[mi][2*np+1], al[mi], &bh[cur][2]);            \
                }                                                              \
                _Pragma("unroll")                                              \
                for (int mi = 0; mi < 4; mi++) {                               \
                    mma16816(acc[mi][2*np],   ah[mi], &bl[cur][0]);            \
                    mma16816(acc[mi][2*np+1], ah[mi], &bl[cur][2]);            \
                }                                                              \
                _Pragma("unroll")                                              \
                for (int mi = 0; mi < 4; mi++) {                               \
                    mma16816(acc[mi][2*np],   ah[mi], &bh[cur][0]);            \
                    mma16816(acc[mi][2*np+1], ah[mi], &bh[cur][2]);            \
                }                                                              \
            }                                                                  \
        }                                                                      \
    }

// ===========================================================================
// QKV GEMM with FUSED bias+RoPE+split epilogue (unchanged from R13)
// ===========================================================================
__global__ void __launch_bounds__(256,1) gemm_qkv(
    const bf16* __restrict__ Ah, const bf16* __restrict__ Al,
    const bf16* __restrict__ Wh, const bf16* __restrict__ Wl,
    const float* __restrict__ bq, const float* __restrict__ bk,
    const float* __restrict__ bv,
    const float* __restrict__ cosp, const float* __restrict__ sinp)
{
    extern __shared__ __align__(16) bf16 sm[];
    const uint32_t smb = smem_u32(sm);
    const int tid  = threadIdx.x;
    const int warp = tid >> 5;
    const int lane = tid & 31;
    const int wr   = warp >> 1;
    const int wc   = warp & 1;
    const int bm   = blockIdx.y * BM3;
    const int bn   = blockIdx.x * BN3;

    float acc[4][8][4];
    #pragma unroll
    for (int mi = 0; mi < 4; mi++)
        #pragma unroll
        for (int nb = 0; nb < 8; nb++)
            #pragma unroll
            for (int c = 0; c < 4; c++) acc[mi][nb][c] = 0.f;

    GEMM_MAINLOOP(Ah, Al, Wh, Wl, HIDDEN, HIDDEN/BK3, 0)

    // ---- fused epilogue: stage C in smem, bias + rope + split, store ----
    __syncthreads();
    float* sC = (float*)sm;               // [256][LDSC]
    {
        const int r0l = wr*64 + (lane >> 2);
        const int c0l = wc*64 + (lane & 3)*2;
        #pragma unroll
        for (int mi = 0; mi < 4; mi++)
            #pragma unroll
            for (int nb = 0; nb < 8; nb++) {
                float* p0 = &sC[(r0l + mi*16)*LDSC + c0l + nb*8];
                float* p1 = &sC[(r0l + mi*16 + 8)*LDSC + c0l + nb*8];
                p0[0] = acc[mi][nb][0]; p0[1] = acc[mi][nb][1];
                p1[0] = acc[mi][nb][2]; p1[1] = acc[mi][nb][3];
            }
    }
    __syncthreads();

    const float qscale = 0.08838834764831845f * 1.4426950408889634f;

    int region, head;
    if (bn < QDIM)              { region = 0; head = bn >> 7; }
    else if (bn < QDIM + KVDIM) { region = 1; head = (bn - QDIM) >> 7; }
    else                        { region = 2; head = (bn - QDIM - KVDIM) >> 7; }

    if (region < 2) {
        bf16* dsth = (region == 0) ? g_Qh : g_Kh;
        bf16* dstl = (region == 0) ? g_Ql : g_Kl;
        const int   nheads = (region == 0) ? NH : NKV;
        const float scmul  = (region == 0) ? qscale : 1.0f;
        const float* bias  = (region == 0) ? bq : bk;
        const int d0 = (tid & 15)*4;
        #pragma unroll 4
        for (int p = 0; p < 16; p++) {
            int t = p*16 + (tid >> 4);
            int token = bm + t;
            int b = token >> 11, s2 = token & (SEQ-1);
            size_t ob = ((size_t)(b*nheads + head)*SEQ + s2)*(size_t)HD;
            bf16 h1v[4], l1v[4], h2v[4], l2v[4];
            #pragma unroll
            for (int dd = 0; dd < 4; dd++) {
                int d = d0 + dd;
                float x1 = sC[t*LDSC + d]      + bias[head*HD + d];
                float x2 = sC[t*LDSC + d + 64] + bias[head*HD + d + 64];
                float cs1 = cosp[(size_t)token*HD + d];
                float sn1 = sinp[(size_t)token*HD + d];
                float cs2 = cosp[(size_t)token*HD + d + 64];
                float sn2 = sinp[(size_t)token*HD + d + 64];
                float o1 = (x1*cs1 - x2*sn1) * scmul;
                float o2 = (x2*cs2 + x1*sn2) * scmul;
                bf16_split(o1, h1v[dd], l1v[dd]);
                bf16_split(o2, h2v[dd], l2v[dd]);
            }
            uint2 u;
            u.x = pack2(h1v[0], h1v[1]); u.y = pack2(h1v[2], h1v[3]);
            *(uint2*)&dsth[ob + d0] = u;
            u.x = pack2(l1v[0], l1v[1]); u.y = pack2(l1v[2], l1v[3]);
            *(uint2*)&dstl[ob + d0] = u;
            u.x = pack2(h2v[0], h2v[1]); u.y = pack2(h2v[2], h2v[3]);
            *(uint2*)&dsth[ob + d0 + 64] = u;
            u.x = pack2(l2v[0], l2v[1]); u.y = pack2(l2v[2], l2v[3]);
            *(uint2*)&dstl[ob + d0 + 64] = u;
        }
    } else {
        const int d0 = (tid & 15)*8;
        #pragma unroll 4
        for (int p = 0; p < 16; p++) {
            int t = p*16 + (tid >> 4);
            int token = bm + t;
            int b = token >> 11, s2 = token & (SEQ-1);
            size_t ob = ((size_t)(b*NKV + head)*SEQ + s2)*(size_t)HD;
            bf16 hv[8], lv[8];
            #pragma unroll
            for (int dd = 0; dd < 8; dd++) {
                int d = d0 + dd;
                float v = sC[t*LDSC + d] + bv[head*HD + d];
                bf16_split(v, hv[dd], lv[dd]);
            }
            uint4 u;
            u.x = pack2(hv[0], hv[1]); u.y = pack2(hv[2], hv[3]);
            u.z = pack2(hv[4], hv[5]); u.w = pack2(hv[6], hv[7]);
            *(uint4*)&g_Vh[ob + d0] = u;
            u.x = pack2(lv[0], lv[1]); u.y = pack2(lv[2], lv[3]);
            u.z = pack2(lv[4], lv[5]); u.w = pack2(lv[6], lv[7]);
            *(uint4*)&g_Vl[ob + d0] = u;
        }
    }
}

// ===========================================================================
// O-projection GEMM: split-K=2, atomic reduce (grid.z = K half)
// ===========================================================================
#define KHALF (HIDDEN/2)   // 1792

__global__ void __launch_bounds__(256,1) gemm_o_sk(
    const bf16* __restrict__ Ah, const bf16* __restrict__ Al,
    const bf16* __restrict__ Wh, const bf16* __restrict__ Wl,
    float* __restrict__ C)
{
    extern __shared__ __align__(16) bf16 sm[];
    const uint32_t smb = smem_u32(sm);
    const int tid  = threadIdx.x;
    const int warp = tid >> 5;
    const int lane = tid & 31;
    const int wr   = warp >> 1;
    const int wc   = warp & 1;
    const int bm   = blockIdx.y * BM3;
    const int bn   = blockIdx.x * BN3;
    const int kb   = blockIdx.z * KHALF;
    const int N    = QDIM;

    float acc[4][8][4];
    #pragma unroll
    for (int mi = 0; mi < 4; mi++)
        #pragma unroll
        for (int nb = 0; nb < 8; nb++)
            #pragma unroll
            for (int c = 0; c < 4; c++) acc[mi][nb][c] = 0.f;

    GEMM_MAINLOOP(Ah, Al, Wh, Wl, HIDDEN, KHALF/BK3, kb)

    {
        const int r0 = bm + wr*64 + (lane >> 2);
        const int c0 = bn + wc*64 + (lane & 3)*2;
        #pragma unroll
        for (int mi = 0; mi < 4; mi++)
            #pragma unroll
            for (int nb = 0; nb < 8; nb++) {
                float* p0 = &C[(size_t)(r0 + mi*16)*N + c0 + nb*8];
                float* p1 = &C[(size_t)(r0 + mi*16 + 8)*N + c0 + nb*8];
                atomicAdd(p0,     acc[mi][nb][0]);
                atomicAdd(p0 + 1, acc[mi][nb][1]);
                atomicAdd(p1,     acc[mi][nb][2]);
                atomicAdd(p1 + 1, acc[mi][nb][3]);
            }
    }
}

// ---------------------------------------------------------------------------
// FlashAttention-2 causal GQA attention (R11 version, unchanged)
// ---------------------------------------------------------------------------
#define FBQ 128
#define FBKV 64
#define FLD 136
#define FQT_HALFS (128*FLD)
#define FKV_HALFS (64*FLD)
#define FSTAGE_HALFS (4*FKV_HALFS)
#define FQ_BYTES (2*FQT_HALFS*2)
#define FSTAGE_BYTES (FSTAGE_HALFS*2)
#define FKV_BYTES (FKV_HALFS*2)
#define FATTN_SMEM (FQ_BYTES + 2*FSTAGE_BYTES)
#define NQT (SEQ/FBQ)

__global__ void __launch_bounds__(256) attn_fa2()
{
    extern __shared__ __align__(16) char smraw[];
    const uint32_t smb = smem_u32(smraw);
    const uint32_t sQh = smb;
    const uint32_t sQl = smb + FQT_HALFS*2;

    const int qt  = (NQT - 1) - blockIdx.x;
    const int h   = blockIdx.y;
    const int b   = blockIdx.z;
    const int kvh = h / NREP;
    const int q0  = qt * FBQ;
    const int tid = threadIdx.x;
    const int warp = tid >> 5;
    const int lane = tid & 31;
    const int R = warp * 16;

    const bf16* Qgh = g_Qh + (size_t)(b*NH  + h  )*SEQ*HD;
    const bf16* Qgl = g_Ql + (size_t)(b*NH  + h  )*SEQ*HD;
    const bf16* Kgh = g_Kh + (size_t)(b*NKV + kvh)*SEQ*HD;
    const bf16* Kgl = g_Kl + (size_t)(b*NKV + kvh)*SEQ*HD;
    const bf16* Vgh = g_Vh + (size_t)(b*NKV + kvh)*SEQ*HD;
    const bf16* Vgl = g_Vl + (size_t)(b*NKV + kvh)*SEQ*HD;

    {
        bf16* qsm = (bf16*)smraw;
        #pragma unroll
        for (int it = 0; it < 16; it++) {
            int c = tid + it*256;
            int t = c >> 11, idx = c & 2047;
            int row = idx >> 4, c16 = idx & 15;
            const bf16* src = (t ? Qgl : Qgh) + (size_t)(q0+row)*HD + c16*8;
            *(uint4*)(qsm + t*FQT_HALFS + row*FLD + c16*8) = *(const uint4*)src;
        }
    }

    auto load_kv = [&](int j, int s) {
        const uint32_t base = smb + FQ_BYTES + (uint32_t)(s*FSTAGE_BYTES);
        #pragma unroll
        for (int it = 0; it < 16; it++) {
            int c = tid + it*256;
            int t = c >> 10, idx = c & 1023;
            int row = idx >> 4, c16 = idx & 15;
            const bf16* src;
            if      (t == 0) src = Kgh;
            else if (t == 1) src = Kgl;
            else if (t == 2) src = Vgh;
            else             src = Vgl;
            cp_async16_sm(base + (uint32_t)((t*FKV_HALFS + row*FLD + c16*8)*2),
                          src + (size_t)(j*FBKV+row)*HD + c16*8);
        }
        asm volatile("cp.async.commit_group;" ::: "memory");
    };

    const int nt = 2*qt + 2;
    load_kv(0, 0);
    __syncthreads();

    float oc[16][4];
    #pragma unroll
    for (int i = 0; i < 16; i++)
        #pragma unroll
        for (int c = 0; c < 4; c++) oc[i][c] = 0.f;
    float m_lo = -INFINITY, m_hi = -INFINITY;
    float l_lo = 0.f, l_hi = 0.f;

    const int row_lo = q0 + R + (lane >> 2);
    const int row_hi = row_lo + 8;

    const int qrow  = R + (lane & 7) + ((lane >> 3) & 1)*8;
    const int qcol8 = ((lane >> 4) & 1)*8;
    const int krow  = (lane & 7) + ((lane >> 4) & 1)*8;
    const int kcol8 = ((lane >> 3) & 1)*8;
    const int vrow  = (lane & 7) + ((lane >> 3) & 1)*8;
    const int vcol8 = ((lane >> 4) & 1)*8;

    for (int j = 0; j < nt; j++) {
        const int s = j & 1;
        asm volatile("cp.async.wait_group 0;" ::: "memory");
        __syncthreads();
        if (j + 1 < nt) load_kv(j + 1, s ^ 1);

        if (j*FBKV > q0 + R + 15) continue;

        const uint32_t stg = smb + FQ_BYTES + (uint32_t)(s*FSTAGE_BYTES);
        const uint32_t sKh = stg;
        const uint32_t sKl = stg + FKV_BYTES;
        const uint32_t sVh = stg + 2*FKV_BYTES;
        const uint32_t sVl = stg + 3*FKV_BYTES;

        float sc[8][4];
        #pragma unroll
        for (int nb = 0; nb < 8; nb++)
            #pragma unroll
            for (int c = 0; c < 4; c++) sc[nb][c] = 0.f;

        #pragma unroll
        for (int ks = 0; ks < 8; ks++) {
            uint32_t qh[4], ql[4];
            uint32_t qo = (uint32_t)((qrow*FLD + ks*16 + qcol8)*2);
            ldsm_x4(qh, sQh + qo);
            ldsm_x4(ql, sQl + qo);
            uint32_t kh[4][4], kl[4][4];
            #pragma unroll
            for (int np = 0; np < 4; np++) {
                uint32_t ko = (uint32_t)(((np*16 + krow)*FLD + ks*16 + kcol8)*2);
                ldsm_x4(kh[np], sKh + ko);
                ldsm_x4(kl[np], sKl + ko);
            }
            #pragma unroll
            for (int np = 0; np < 4; np++) {
                mma16816(sc[2*np],   ql, &kh[np][0]);
                mma16816(sc[2*np+1], ql, &kh[np][2]);
            }
            #pragma unroll
            for (int np = 0; np < 4; np++) {
                mma16816(sc[2*np],   qh, &kl[np][0]);
                mma16816(sc[2*np+1], qh, &kl[np][2]);
            }
            #pragma unroll
            for (int np = 0; np < 4; np++) {
                mma16816(sc[2*np],   qh, &kh[np][0]);
                mma16816(sc[2*np+1], qh, &kh[np][2]);
            }
        }

        const bool masked = (j*FBKV + 63 > q0 + R);
        const int cb = j*FBKV + (lane & 3)*2;
        float tmlo = -INFINITY, tmhi = -INFINITY;
        if (!masked) {
            #pragma unroll
            for (int nb = 0; nb < 8; nb++) {
                tmlo = fmaxf(tmlo, fmaxf(sc[nb][0], sc[nb][1]));
                tmhi = fmaxf(tmhi, fmaxf(sc[nb][2], sc[nb][3]));
            }
        } else {
            #pragma unroll
            for (int nb = 0; nb < 8; nb++) {
                int c0 = cb + nb*8, c1 = c0 + 1;
                if (c0 <= row_lo) tmlo = fmaxf(tmlo, sc[nb][0]);
                if (c1 <= row_lo) tmlo = fmaxf(tmlo, sc[nb][1]);
                if (c0 <= row_hi) tmhi = fmaxf(tmhi, sc[nb][2]);
                if (c1 <= row_hi) tmhi = fmaxf(tmhi, sc[nb][3]);
            }
        }
        tmlo = fmaxf(tmlo, __shfl_xor_sync(0xffffffffu, tmlo, 1));
        tmlo = fmaxf(tmlo, __shfl_xor_sync(0xffffffffu, tmlo, 2));
        tmhi = fmaxf(tmhi, __shfl_xor_sync(0xffffffffu, tmhi, 1));
        tmhi = fmaxf(tmhi, __shfl_xor_sync(0xffffffffu, tmhi, 2));

        float mn_lo = fmaxf(m_lo, tmlo);
        float mn_hi = fmaxf(m_hi, tmhi);
        float alpha_lo = exp2f(m_lo - mn_lo);
        float alpha_hi = exp2f(m_hi - mn_hi);
        m_lo = mn_lo; m_hi = mn_hi;
        #pragma unroll
        for (int nb = 0; nb < 16; nb++) {
            oc[nb][0] *= alpha_lo; oc[nb][1] *= alpha_lo;
            oc[nb][2] *= alpha_hi; oc[nb][3] *= alpha_hi;
        }

        float slo = 0.f, shi = 0.f;
        #pragma unroll
        for (int nb = 0; nb < 8; nb++) {
            float p0 = exp2f(sc[nb][0] - mn_lo);
            float p1 = exp2f(sc[nb][1] - mn_lo);
            float p2 = exp2f(sc[nb][2] - mn_hi);
            float p3 = exp2f(sc[nb][3] - mn_hi);
            if (masked) {
                int c0 = cb + nb*8, c1 = c0 + 1;
                if (c0 > row_lo) p0 = 0.f;
                if (c1 > row_lo) p1 = 0.f;
                if (c0 > row_hi) p2 = 0.f;
                if (c1 > row_hi) p3 = 0.f;
            }
            sc[nb][0] = p0; sc[nb][1] = p1; sc[nb][2] = p2; sc[nb][3] = p3;
            slo += p0 + p1; shi += p2 + p3;
        }
        slo += __shfl_xor_sync(0xffffffffu, slo, 1);
        slo += __shfl_xor_sync(0xffffffffu, slo, 2);
        shi += __shfl_xor_sync(0xffffffffu, shi, 1);
        shi += __shfl_xor_sync(0xffffffffu, shi, 2);
        l_lo = l_lo * alpha_lo + slo;
        l_hi = l_hi * alpha_hi + shi;

        #pragma unroll
        for (int ks2 = 0; ks2 < 4; ks2++) {
            uint32_t pah[4], pal[4];
            #pragma unroll
            for (int half = 0; half < 2; half++) {
                const float* f = sc[2*ks2 + half];
                bf16 h0, l0, h1, l1, h2, l2, h3, l3;
                bf16_split(f[0], h0, l0);
                bf16_split(f[1], h1, l1);
                bf16_split(f[2], h2, l2);
                bf16_split(f[3], h3, l3);
                pah[half*2 + 0] = pack2(h0, h1);
                pah[half*2 + 1] = pack2(h2, h3);
                pal[half*2 + 0] = pack2(l0, l1);
                pal[half*2 + 1] = pack2(l2, l3);
            }
            #pragma unroll
            for (int npp = 0; npp < 4; npp++) {
                uint32_t vh0[4], vl0[4], vh1[4], vl1[4];
                uint32_t vo0 = (uint32_t)(((ks2*16 + vrow)*FLD + (2*npp)*16 + vcol8)*2);
                uint32_t vo1 = (uint32_t)(((ks2*16 + vrow)*FLD + (2*npp+1)*16 + vcol8)*2);
                ldsm_x4t(vh0, sVh + vo0);
                ldsm_x4t(vl0, sVl + vo0);
                ldsm_x4t(vh1, sVh + vo1);
                ldsm_x4t(vl1, sVl + vo1);
                float* o0 = oc[4*npp + 0];
                float* o1 = oc[4*npp + 1];
                float* o2 = oc[4*npp + 2];
                float* o3 = oc[4*npp + 3];
                mma16816(o0, pal, &vh0[0]);
                mma16816(o1, pal, &vh0[2]);
                mma16816(o2, pal, &vh1[0]);
                mma16816(o3, pal, &vh1[2]);
                mma16816(o0, pah, &vl0[0]);
                mma16816(o1, pah, &vl0[2]);
                mma16816(o2, pah, &vl1[0]);
                mma16816(o3, pah, &vl1[2]);
                mma16816(o0, pah, &vh0[0]);
                mma16816(o1, pah, &vh0[2]);
                mma16816(o2, pah, &vh1[0]);
                mma16816(o3, pah, &vh1[2]);
            }
        }
    }

    {
        float inv_lo = 1.f / l_lo;
        float inv_hi = 1.f / l_hi;
        size_t base_lo = ((size_t)(b*SEQ + row_lo))*QDIM + h*HD;
        size_t base_hi = ((size_t)(b*SEQ + row_hi))*QDIM + h*HD;
        #pragma unroll
        for (int nb = 0; nb < 16; nb++) {
            int n0 = nb*8 + (lane & 3)*2;
            float f0 = oc[nb][0]*inv_lo, f1 = oc[nb][1]*inv_lo;
            float f2 = oc[nb][2]*inv_hi, f3 = oc[nb][3]*inv_hi;
            bf16 h0, l0, h1, l1, h2, l2, h3, l3;
            bf16_split(f0, h0, l0);
            bf16_split(f1, h1, l1);
            bf16_split(f2, h2, l2);
            bf16_split(f3, h3, l3);
            *(uint32_t*)&g_Ah[base_lo + n0] = pack2(h0, h1);
            *(uint32_t*)&g_Al[base_lo + n0] = pack2(l0, l1);
            *(uint32_t*)&g_Ah[base_hi + n0] = pack2(h2, h3);
            *(uint32_t*)&g_Al[base_hi + n0] = pack2(l2, l3);
        }
    }
}

// ---------------------------------------------------------------------------
// launch
// ---------------------------------------------------------------------------
extern "C" void kernel_launch(void* const* d_in, const int* in_sizes, int n_in,
                              void* d_out, int out_size)
{
    (void)in_sizes; (void)n_in; (void)out_size;
    const float* hs   = (const float*)d_in[0];
    const float* cosp = (const float*)d_in[1];
    const float* sinp = (const float*)d_in[2];
    const float* Wq   = (const float*)d_in[3];
    const float* bq   = (const float*)d_in[4];
    const float* Wk   = (const float*)d_in[5];
    const float* bk   = (const float*)d_in[6];
    const float* Wv   = (const float*)d_in[7];
    const float* bv   = (const float*)d_in[8];
    const float* Wo   = (const float*)d_in[9];
    float* out = (float*)d_out;

    bf16 *hsh, *hsl, *Wch, *Wcl, *Woh, *Wol, *Ah, *Al;
    cudaGetSymbolAddress((void**)&hsh, g_hsh);
    cudaGetSymbolAddress((void**)&hsl, g_hsl);
    cudaGetSymbolAddress((void**)&Wch, g_Wch);
    cudaGetSymbolAddress((void**)&Wcl, g_Wcl);
    cudaGetSymbolAddress((void**)&Woh, g_Woh);
    cudaGetSymbolAddress((void**)&Wol, g_Wol);
    cudaGetSymbolAddress((void**)&Ah,  g_Ah);
    cudaGetSymbolAddress((void**)&Al,  g_Al);

    cudaFuncSetAttribute(gemm_qkv,
                         cudaFuncAttributeMaxDynamicSharedMemorySize,
                         SMEM3_BYTES);
    cudaFuncSetAttribute(gemm_o_sk,
                         cudaFuncAttributeMaxDynamicSharedMemorySize,
                         SMEM3_BYTES);
    cudaFuncSetAttribute(attn_fa2,
                         cudaFuncAttributeMaxDynamicSharedMemorySize,
                         FATTN_SMEM);

    split_all<<<SP_GRID, 256>>>((const float4*)hs, (const float4*)Wq,
                                (const float4*)Wk, (const float4*)Wv,
                                (const float4*)Wo);
    zero_out<<<(unsigned)(((size_t)M_TOK*QDIM/4 + 255)/256), 256>>>(
        (float4*)out, (size_t)M_TOK*QDIM/4);

    gemm_qkv<<<dim3(NDIMC/BN3, M_TOK/BM3), 256, SMEM3_BYTES>>>(
        hsh, hsl, Wch, Wcl, bq, bk, bv, cosp, sinp);
    attn_fa2<<<dim3(NQT, NH, BATCH), 256, FATTN_SMEM>>>();
    gemm_o_sk<<<dim3(QDIM/BN3, M_TOK/BM3, 2), 256, SMEM3_BYTES>>>(
        Ah, Al, Woh, Wol, out);
}

// round 15
// speedup vs baseline: 1.0215x; 1.0215x over previous
#include <cuda_runtime.h>
#include <cuda_bf16.h>
#include <mma.h>
#include <math.h>
#include <cstdint>
#include <cstddef>

#define HIDDEN 3584
#define NH 28
#define NKV 4
#define HD 128
#define NREP 7
#define BATCH 2
#define SEQ 2048
#define M_TOK (BATCH*SEQ)   // 4096
#define QDIM (NH*HD)        // 3584
#define KVDIM (NKV*HD)      // 512
#define NDIMC (QDIM + 2*KVDIM)   // 4608

typedef __nv_bfloat16 bf16;

// ---------------------------------------------------------------------------
// Scratch
// ---------------------------------------------------------------------------
__device__ __align__(128) bf16 g_hsh[(size_t)M_TOK*HIDDEN];
__device__ __align__(128) bf16 g_hsl[(size_t)M_TOK*HIDDEN];
__device__ __align__(128) bf16 g_Wch[(size_t)NDIMC*HIDDEN];
__device__ __align__(128) bf16 g_Wcl[(size_t)NDIMC*HIDDEN];
__device__ __align__(128) bf16 g_Woh[(size_t)HIDDEN*QDIM];
__device__ __align__(128) bf16 g_Wol[(size_t)HIDDEN*QDIM];

__device__ __align__(128) bf16 g_Qh[(size_t)M_TOK*QDIM];   // [B][NH][S][D]
__device__ __align__(128) bf16 g_Ql[(size_t)M_TOK*QDIM];
__device__ __align__(128) bf16 g_Kh[(size_t)M_TOK*KVDIM];  // [B][NKV][S][D]
__device__ __align__(128) bf16 g_Kl[(size_t)M_TOK*KVDIM];
__device__ __align__(128) bf16 g_Vh[(size_t)M_TOK*KVDIM];
__device__ __align__(128) bf16 g_Vl[(size_t)M_TOK*KVDIM];
__device__ __align__(128) bf16 g_Ah[(size_t)M_TOK*QDIM];
__device__ __align__(128) bf16 g_Al[(size_t)M_TOK*QDIM];

// ---------------------------------------------------------------------------
// helpers
// ---------------------------------------------------------------------------
__device__ __forceinline__ void bf16_split(float x, bf16& hi, bf16& lo) {
    hi = __float2bfloat16(x);
    lo = __float2bfloat16(x - __bfloat162float(hi));
}
__device__ __forceinline__ uint32_t smem_u32(const void* p) {
    return (uint32_t)__cvta_generic_to_shared(p);
}
__device__ __forceinline__ void cp_async16_sm(uint32_t s, const void* g) {
    asm volatile("cp.async.cg.shared.global [%0], [%1], 16;\n"
                 :: "r"(s), "l"(g));
}
__device__ __forceinline__ void ldsm_x4(uint32_t r[4], uint32_t addr) {
    asm volatile("ldmatrix.sync.aligned.m8n8.x4.shared.b16 {%0,%1,%2,%3}, [%4];"
        : "=r"(r[0]), "=r"(r[1]), "=r"(r[2]), "=r"(r[3]) : "r"(addr));
}
__device__ __forceinline__ void ldsm_x4t(uint32_t r[4], uint32_t addr) {
    asm volatile("ldmatrix.sync.aligned.m8n8.x4.trans.shared.b16 {%0,%1,%2,%3}, [%4];"
        : "=r"(r[0]), "=r"(r[1]), "=r"(r[2]), "=r"(r[3]) : "r"(addr));
}
__device__ __forceinline__ void mma16816(float d[4], const uint32_t a[4],
                                         const uint32_t b[2]) {
    asm volatile(
        "mma.sync.aligned.m16n8k16.row.col.f32.bf16.bf16.f32 "
        "{%0,%1,%2,%3}, {%4,%5,%6,%7}, {%8,%9}, {%0,%1,%2,%3};"
        : "+f"(d[0]), "+f"(d[1]), "+f"(d[2]), "+f"(d[3])
        : "r"(a[0]), "r"(a[1]), "r"(a[2]), "r"(a[3]), "r"(b[0]), "r"(b[1]));
}
__device__ __forceinline__ uint32_t pack2(bf16 a, bf16 b) {
    __nv_bfloat162 v(a, b);
    return *(uint32_t*)&v;
}

// ---------------------------------------------------------------------------
// fused split kernel: all 5 tensors in one launch
// ---------------------------------------------------------------------------
#define SP_N0 ((size_t)M_TOK*HIDDEN/4)                 // hs
#define SP_N1 (SP_N0 + (size_t)QDIM*HIDDEN/4)          // Wq
#define SP_N2 (SP_N1 + (size_t)KVDIM*HIDDEN/4)         // Wk
#define SP_N3 (SP_N2 + (size_t)KVDIM*HIDDEN/4)         // Wv
#define SP_N4 (SP_N3 + (size_t)HIDDEN*QDIM/4)          // Wo
#define SP_GRID ((unsigned)((SP_N4 + 255) / 256))

__global__ void __launch_bounds__(256) split_all(
    const float4* __restrict__ hs, const float4* __restrict__ Wq,
    const float4* __restrict__ Wk, const float4* __restrict__ Wv,
    const float4* __restrict__ Wo)
{
    size_t i = (size_t)blockIdx.x*256 + threadIdx.x;
    if (i >= SP_N4) return;
    const float4* src;
    bf16 *hi, *lo;
    size_t j;
    if (i < SP_N0)      { j = i;         src = hs; hi = g_hsh; lo = g_hsl; }
    else if (i < SP_N1) { j = i - SP_N0; src = Wq; hi = g_Wch; lo = g_Wcl; }
    else if (i < SP_N2) { j = i - SP_N1; src = Wk;
                          hi = g_Wch + (size_t)QDIM*HIDDEN;
                          lo = g_Wcl + (size_t)QDIM*HIDDEN; }
    else if (i < SP_N3) { j = i - SP_N2; src = Wv;
                          hi = g_Wch + (size_t)(QDIM+KVDIM)*HIDDEN;
                          lo = g_Wcl + (size_t)(QDIM+KVDIM)*HIDDEN; }
    else                { j = i - SP_N3; src = Wo; hi = g_Woh; lo = g_Wol; }
    float4 v = src[j];
    bf16 hx, lx, hy, ly, hz, lz, hw, lw;
    bf16_split(v.x, hx, lx);
    bf16_split(v.y, hy, ly);
    bf16_split(v.z, hz, lz);
    bf16_split(v.w, hw, lw);
    __nv_bfloat162* h2 = (__nv_bfloat162*)hi;
    __nv_bfloat162* l2 = (__nv_bfloat162*)lo;
    h2[2*j]   = __nv_bfloat162(hx, hy);
    h2[2*j+1] = __nv_bfloat162(hz, hw);
    l2[2*j]   = __nv_bfloat162(lx, ly);
    l2[2*j+1] = __nv_bfloat162(lz, lw);
}

// ===========================================================================
// Shared GEMM mainloop config: BM=256 BN=128 BK=64, 8 warps, 64x64 warp tile
// ===========================================================================
#define BM3 256
#define BN3 128
#define BK3 64
#define LDT3 72
#define OFF3_AH 0
#define OFF3_AL (BM3*LDT3)
#define OFF3_BH (2*BM3*LDT3)
#define OFF3_BL (2*BM3*LDT3 + BN3*LDT3)
#define STAGE3_HALFS (2*BM3*LDT3 + 2*BN3*LDT3)   // 55296
#define SMEM3_BYTES (2*STAGE3_HALFS*2)           // 221184
#define LDSC 132                                 // fp32 C-tile stride (epilogue)

#define GEMM_MAINLOOP(Ahp, Alp, Whp, Wlp, Kdim)                                \
    auto load_chunk = [&](int chunk, int slot) {                               \
        const int k0 = chunk * BK3;                                            \
        const uint32_t base = smb + (uint32_t)(slot*STAGE3_HALFS*2);           \
        _Pragma("unroll")                                                      \
        for (int it = 0; it < 24; it++) {                                      \
            int c = tid + it*256;                                              \
            const bf16* g;                                                     \
            uint32_t soff;                                                     \
            if (c < 4096) {                                                    \
                int t = c >> 11, idx = c & 2047;                               \
                int row = idx >> 3, c16 = idx & 7;                             \
                g = (t ? Alp : Ahp) + (size_t)(bm+row)*(Kdim) + k0 + c16*8;    \
                soff = (uint32_t)(((t ? OFF3_AL : OFF3_AH) + row*LDT3 + c16*8) * 2); \
            } else {                                                           \
                int d = c - 4096;                                              \
                int t = d >> 10, idx = d & 1023;                               \
                int row = idx >> 3, c16 = idx & 7;                             \
                g = (t ? Wlp : Whp) + (size_t)(bn+row)*(Kdim) + k0 + c16*8;    \
                soff = (uint32_t)(((t ? OFF3_BL : OFF3_BH) + row*LDT3 + c16*8) * 2); \
            }                                                                  \
            cp_async16_sm(base + soff, g);                                     \
        }                                                                      \
        asm volatile("cp.async.commit_group;" ::: "memory");                   \
    };                                                                         \
    const int arow  = wr*64 + (lane & 7) + ((lane >> 3) & 1)*8;                \
    const int acol8 = ((lane >> 4) & 1)*8;                                     \
    const int brow  = wc*64 + (lane & 7) + ((lane >> 4) & 1)*8;                \
    const int bcol8 = ((lane >> 3) & 1)*8;                                     \
    const int T = (Kdim) / BK3;                                                \
    load_chunk(0, 0);                                                          \
    for (int i = 0; i < T; i++) {                                              \
        const int slot = i & 1;                                                \
        asm volatile("cp.async.wait_group 0;" ::: "memory");                   \
        __syncthreads();                                                       \
        if (i + 1 < T) load_chunk(i + 1, slot ^ 1);                            \
        const uint32_t st = smb + (uint32_t)(slot*STAGE3_HALFS*2);             \
        const uint32_t sAh = st + OFF3_AH*2;                                   \
        const uint32_t sAl = st + OFF3_AL*2;                                   \
        const uint32_t sBh = st + OFF3_BH*2;                                   \
        const uint32_t sBl = st + OFF3_BL*2;                                   \
        _Pragma("unroll")                                                      \
        for (int ks = 0; ks < 4; ks++) {                                       \
            const int kofs = ks*16;                                            \
            uint32_t ah[4][4], al[4][4];                                       \
            _Pragma("unroll")                                                  \
            for (int mi = 0; mi < 4; mi++) {                                   \
                uint32_t ao = (uint32_t)(((arow + mi*16)*LDT3 + kofs + acol8)*2); \
                ldsm_x4(ah[mi], sAh + ao);                                     \
                ldsm_x4(al[mi], sAl + ao);                                     \
            }                                                                  \
            uint32_t bh[2][4], bl[2][4];                                       \
            {                                                                  \
                uint32_t bo = (uint32_t)((brow*LDT3 + kofs + bcol8)*2);        \
                ldsm_x4(bh[0], sBh + bo);                                      \
                ldsm_x4(bl[0], sBl + bo);                                      \
            }                                                                  \
            _Pragma("unroll")                                                  \
            for (int np = 0; np < 4; np++) {                                   \
                const int cur = np & 1;                                        \
                if (np < 3) {                                                  \
                    uint32_t bo = (uint32_t)(((brow + (np+1)*16)*LDT3 + kofs + bcol8)*2); \
                    ldsm_x4(bh[cur ^ 1], sBh + bo);                            \
                    ldsm_x4(bl[cur ^ 1], sBl + bo);                            \
                }                                                              \
                _Pragma("unroll")                                              \
                for (int mi = 0; mi < 4; mi++) {                               \
                    mma16816(acc[mi][2*np],   al[mi], &bh[cur][0]);            \
                    mma16816(acc[mi][2*np+1], al[mi], &bh[cur][2]);            \
                }                                                              \
                _Pragma("unroll")                                              \
                for (int mi = 0; mi < 4; mi++) {                               \
                    mma16816(acc[mi][2*np],   ah[mi], &bl[cur][0]);            \
                    mma16816(acc[mi][2*np+1], ah[mi], &bl[cur][2]);            \
                }                                                              \
                _Pragma("unroll")                                              \
                for (int mi = 0; mi < 4; mi++) {                               \
                    mma16816(acc[mi][2*np],   ah[mi], &bh[cur][0]);            \
                    mma16816(acc[mi][2*np+1], ah[mi], &bh[cur][2]);            \
                }                                                              \
            }                                                                  \
        }                                                                      \
    }

// ===========================================================================
// QKV GEMM with FUSED bias+RoPE+split epilogue
// ===========================================================================
__global__ void __launch_bounds__(256,1) gemm_qkv(
    const bf16* __restrict__ Ah, const bf16* __restrict__ Al,
    const bf16* __restrict__ Wh, const bf16* __restrict__ Wl,
    const float* __restrict__ bq, const float* __restrict__ bk,
    const float* __restrict__ bv,
    const float* __restrict__ cosp, const float* __restrict__ sinp)
{
    extern __shared__ __align__(16) bf16 sm[];
    const uint32_t smb = smem_u32(sm);
    const int tid  = threadIdx.x;
    const int warp = tid >> 5;
    const int lane = tid & 31;
    const int wr   = warp >> 1;
    const int wc   = warp & 1;
    const int bm   = blockIdx.y * BM3;
    const int bn   = blockIdx.x * BN3;

    float acc[4][8][4];
    #pragma unroll
    for (int mi = 0; mi < 4; mi++)
        #pragma unroll
        for (int nb = 0; nb < 8; nb++)
            #pragma unroll
            for (int c = 0; c < 4; c++) acc[mi][nb][c] = 0.f;

    GEMM_MAINLOOP(Ah, Al, Wh, Wl, HIDDEN)

    __syncthreads();
    float* sC = (float*)sm;               // [256][LDSC]
    {
        const int r0l = wr*64 + (lane >> 2);
        const int c0l = wc*64 + (lane & 3)*2;
        #pragma unroll
        for (int mi = 0; mi < 4; mi++)
            #pragma unroll
            for (int nb = 0; nb < 8; nb++) {
                float* p0 = &sC[(r0l + mi*16)*LDSC + c0l + nb*8];
                float* p1 = &sC[(r0l + mi*16 + 8)*LDSC + c0l + nb*8];
                p0[0] = acc[mi][nb][0]; p0[1] = acc[mi][nb][1];
                p1[0] = acc[mi][nb][2]; p1[1] = acc[mi][nb][3];
            }
    }
    __syncthreads();

    const float qscale = 0.08838834764831845f * 1.4426950408889634f;

    int region, head;
    if (bn < QDIM)              { region = 0; head = bn >> 7; }
    else if (bn < QDIM + KVDIM) { region = 1; head = (bn - QDIM) >> 7; }
    else                        { region = 2; head = (bn - QDIM - KVDIM) >> 7; }

    if (region < 2) {
        bf16* dsth = (region == 0) ? g_Qh : g_Kh;
        bf16* dstl = (region == 0) ? g_Ql : g_Kl;
        const int   nheads = (region == 0) ? NH : NKV;
        const float scmul  = (region == 0) ? qscale : 1.0f;
        const float* bias  = (region == 0) ? bq : bk;
        const int d0 = (tid & 15)*4;
        #pragma unroll 4
        for (int p = 0; p < 16; p++) {
            int t = p*16 + (tid >> 4);
            int token = bm + t;
            int b = token >> 11, s2 = token & (SEQ-1);
            size_t ob = ((size_t)(b*nheads + head)*SEQ + s2)*(size_t)HD;
            bf16 h1v[4], l1v[4], h2v[4], l2v[4];
            #pragma unroll
            for (int dd = 0; dd < 4; dd++) {
                int d = d0 + dd;
                float x1 = sC[t*LDSC + d]      + bias[head*HD + d];
                float x2 = sC[t*LDSC + d + 64] + bias[head*HD + d + 64];
                float cs1 = cosp[(size_t)token*HD + d];
                float sn1 = sinp[(size_t)token*HD + d];
                float cs2 = cosp[(size_t)token*HD + d + 64];
                float sn2 = sinp[(size_t)token*HD + d + 64];
                float o1 = (x1*cs1 - x2*sn1) * scmul;
                float o2 = (x2*cs2 + x1*sn2) * scmul;
                bf16_split(o1, h1v[dd], l1v[dd]);
                bf16_split(o2, h2v[dd], l2v[dd]);
            }
            uint2 u;
            u.x = pack2(h1v[0], h1v[1]); u.y = pack2(h1v[2], h1v[3]);
            *(uint2*)&dsth[ob + d0] = u;
            u.x = pack2(l1v[0], l1v[1]); u.y = pack2(l1v[2], l1v[3]);
            *(uint2*)&dstl[ob + d0] = u;
            u.x = pack2(h2v[0], h2v[1]); u.y = pack2(h2v[2], h2v[3]);
            *(uint2*)&dsth[ob + d0 + 64] = u;
            u.x = pack2(l2v[0], l2v[1]); u.y = pack2(l2v[2], l2v[3]);
            *(uint2*)&dstl[ob + d0 + 64] = u;
        }
    } else {
        const int d0 = (tid & 15)*8;
        #pragma unroll 4
        for (int p = 0; p < 16; p++) {
            int t = p*16 + (tid >> 4);
            int token = bm + t;
            int b = token >> 11, s2 = token & (SEQ-1);
            size_t ob = ((size_t)(b*NKV + head)*SEQ + s2)*(size_t)HD;
            bf16 hv[8], lv[8];
            #pragma unroll
            for (int dd = 0; dd < 8; dd++) {
                int d = d0 + dd;
                float v = sC[t*LDSC + d] + bv[head*HD + d];
                bf16_split(v, hv[dd], lv[dd]);
            }
            uint4 u;
            u.x = pack2(hv[0], hv[1]); u.y = pack2(hv[2], hv[3]);
            u.z = pack2(hv[4], hv[5]); u.w = pack2(hv[6], hv[7]);
            *(uint4*)&g_Vh[ob + d0] = u;
            u.x = pack2(lv[0], lv[1]); u.y = pack2(lv[2], lv[3]);
            u.z = pack2(lv[4], lv[5]); u.w = pack2(lv[6], lv[7]);
            *(uint4*)&g_Vl[ob + d0] = u;
        }
    }
}

// ===========================================================================
// O-projection GEMM: BM=256 plain (proven R13 shape)
// ===========================================================================
__global__ void __launch_bounds__(256,1) gemm_o(
    const bf16* __restrict__ Ah, const bf16* __restrict__ Al,
    const bf16* __restrict__ Wh, const bf16* __restrict__ Wl,
    float* __restrict__ C)
{
    extern __shared__ __align__(16) bf16 sm[];
    const uint32_t smb = smem_u32(sm);
    const int tid  = threadIdx.x;
    const int warp = tid >> 5;
    const int lane = tid & 31;
    const int wr   = warp >> 1;
    const int wc   = warp & 1;
    const int bm   = blockIdx.y * BM3;
    const int bn   = blockIdx.x * BN3;
    const int N    = QDIM;

    float acc[4][8][4];
    #pragma unroll
    for (int mi = 0; mi < 4; mi++)
        #pragma unroll
        for (int nb = 0; nb < 8; nb++)
            #pragma unroll
            for (int c = 0; c < 4; c++) acc[mi][nb][c] = 0.f;

    GEMM_MAINLOOP(Ah, Al, Wh, Wl, HIDDEN)

    {
        const int r0 = bm + wr*64 + (lane >> 2);
        const int c0 = bn + wc*64 + (lane & 3)*2;
        #pragma unroll
        for (int mi = 0; mi < 4; mi++)
            #pragma unroll
            for (int nb = 0; nb < 8; nb++) {
                float* p0 = &C[(size_t)(r0 + mi*16)*N + c0 + nb*8];
                float* p1 = &C[(size_t)(r0 + mi*16 + 8)*N + c0 + nb*8];
                *(float2*)p0 = make_float2(acc[mi][nb][0], acc[mi][nb][1]);
                *(float2*)p1 = make_float2(acc[mi][nb][2], acc[mi][nb][3]);
            }
    }
}

// ---------------------------------------------------------------------------
// FlashAttention-2 causal GQA attention; exp/split interleaved into PV loop
// ---------------------------------------------------------------------------
#define FBQ 128
#define FBKV 64
#define FLD 136
#define FQT_HALFS (128*FLD)
#define FKV_HALFS (64*FLD)
#define FSTAGE_HALFS (4*FKV_HALFS)
#define FQ_BYTES (2*FQT_HALFS*2)
#define FSTAGE_BYTES (FSTAGE_HALFS*2)
#define FKV_BYTES (FKV_HALFS*2)
#define FATTN_SMEM (FQ_BYTES + 2*FSTAGE_BYTES)
#define NQT (SEQ/FBQ)

__global__ void __launch_bounds__(256) attn_fa2()
{
    extern __shared__ __align__(16) char smraw[];
    const uint32_t smb = smem_u32(smraw);
    const uint32_t sQh = smb;
    const uint32_t sQl = smb + FQT_HALFS*2;

    const int qt  = (NQT - 1) - blockIdx.x;
    const int h   = blockIdx.y;
    const int b   = blockIdx.z;
    const int kvh = h / NREP;
    const int q0  = qt * FBQ;
    const int tid = threadIdx.x;
    const int warp = tid >> 5;
    const int lane = tid & 31;
    const int R = warp * 16;

    const bf16* Qgh = g_Qh + (size_t)(b*NH  + h  )*SEQ*HD;
    const bf16* Qgl = g_Ql + (size_t)(b*NH  + h  )*SEQ*HD;
    const bf16* Kgh = g_Kh + (size_t)(b*NKV + kvh)*SEQ*HD;
    const bf16* Kgl = g_Kl + (size_t)(b*NKV + kvh)*SEQ*HD;
    const bf16* Vgh = g_Vh + (size_t)(b*NKV + kvh)*SEQ*HD;
    const bf16* Vgl = g_Vl + (size_t)(b*NKV + kvh)*SEQ*HD;

    {
        bf16* qsm = (bf16*)smraw;
        #pragma unroll
        for (int it = 0; it < 16; it++) {
            int c = tid + it*256;
            int t = c >> 11, idx = c & 2047;
            int row = idx >> 4, c16 = idx & 15;
            const bf16* src = (t ? Qgl : Qgh) + (size_t)(q0+row)*HD + c16*8;
            *(uint4*)(qsm + t*FQT_HALFS + row*FLD + c16*8) = *(const uint4*)src;
        }
    }

    auto load_kv = [&](int j, int s) {
        const uint32_t base = smb + FQ_BYTES + (uint32_t)(s*FSTAGE_BYTES);
        #pragma unroll
        for (int it = 0; it < 16; it++) {
            int c = tid + it*256;
            int t = c >> 10, idx = c & 1023;
            int row = idx >> 4, c16 = idx & 15;
            const bf16* src;
            if      (t == 0) src = Kgh;
            else if (t == 1) src = Kgl;
            else if (t == 2) src = Vgh;
            else             src = Vgl;
            cp_async16_sm(base + (uint32_t)((t*FKV_HALFS + row*FLD + c16*8)*2),
                          src + (size_t)(j*FBKV+row)*HD + c16*8);
        }
        asm volatile("cp.async.commit_group;" ::: "memory");
    };

    const int nt = 2*qt + 2;
    load_kv(0, 0);
    __syncthreads();

    float oc[16][4];
    #pragma unroll
    for (int i = 0; i < 16; i++)
        #pragma unroll
        for (int c = 0; c < 4; c++) oc[i][c] = 0.f;
    float m_lo = -INFINITY, m_hi = -INFINITY;
    float l_lo = 0.f, l_hi = 0.f;

    const int row_lo = q0 + R + (lane >> 2);
    const int row_hi = row_lo + 8;

    const int qrow  = R + (lane & 7) + ((lane >> 3) & 1)*8;
    const int qcol8 = ((lane >> 4) & 1)*8;
    const int krow  = (lane & 7) + ((lane >> 4) & 1)*8;
    const int kcol8 = ((lane >> 3) & 1)*8;
    const int vrow  = (lane & 7) + ((lane >> 3) & 1)*8;
    const int vcol8 = ((lane >> 4) & 1)*8;

    for (int j = 0; j < nt; j++) {
        const int s = j & 1;
        asm volatile("cp.async.wait_group 0;" ::: "memory");
        __syncthreads();
        if (j + 1 < nt) load_kv(j + 1, s ^ 1);

        if (j*FBKV > q0 + R + 15) continue;

        const uint32_t stg = smb + FQ_BYTES + (uint32_t)(s*FSTAGE_BYTES);
        const uint32_t sKh = stg;
        const uint32_t sKl = stg + FKV_BYTES;
        const uint32_t sVh = stg + 2*FKV_BYTES;
        const uint32_t sVl = stg + 3*FKV_BYTES;

        float sc[8][4];
        #pragma unroll
        for (int nb = 0; nb < 8; nb++)
            #pragma unroll
            for (int c = 0; c < 4; c++) sc[nb][c] = 0.f;

        #pragma unroll
        for (int ks = 0; ks < 8; ks++) {
            uint32_t qh[4], ql[4];
            uint32_t qo = (uint32_t)((qrow*FLD + ks*16 + qcol8)*2);
            ldsm_x4(qh, sQh + qo);
            ldsm_x4(ql, sQl + qo);
            uint32_t kh[4][4], kl[4][4];
            #pragma unroll
            for (int np = 0; np < 4; np++) {
                uint32_t ko = (uint32_t)(((np*16 + krow)*FLD + ks*16 + kcol8)*2);
                ldsm_x4(kh[np], sKh + ko);
                ldsm_x4(kl[np], sKl + ko);
            }
            #pragma unroll
            for (int np = 0; np < 4; np++) {
                mma16816(sc[2*np],   ql, &kh[np][0]);
                mma16816(sc[2*np+1], ql, &kh[np][2]);
            }
            #pragma unroll
            for (int np = 0; np < 4; np++) {
                mma16816(sc[2*np],   qh, &kl[np][0]);
                mma16816(sc[2*np+1], qh, &kl[np][2]);
            }
            #pragma unroll
            for (int np = 0; np < 4; np++) {
                mma16816(sc[2*np],   qh, &kh[np][0]);
                mma16816(sc[2*np+1], qh, &kh[np][2]);
            }
        }

        const bool masked = (j*FBKV + 63 > q0 + R);
        const int cb = j*FBKV + (lane & 3)*2;
        float tmlo = -INFINITY, tmhi = -INFINITY;
        if (!masked) {
            #pragma unroll
            for (int nb = 0; nb < 8; nb++) {
                tmlo = fmaxf(tmlo, fmaxf(sc[nb][0], sc[nb][1]));
                tmhi = fmaxf(tmhi, fmaxf(sc[nb][2], sc[nb][3]));
            }
        } else {
            #pragma unroll
            for (int nb = 0; nb < 8; nb++) {
                int c0 = cb + nb*8, c1 = c0 + 1;
                if (c0 <= row_lo) tmlo = fmaxf(tmlo, sc[nb][0]);
                if (c1 <= row_lo) tmlo = fmaxf(tmlo, sc[nb][1]);
                if (c0 <= row_hi) tmhi = fmaxf(tmhi, sc[nb][2]);
                if (c1 <= row_hi) tmhi = fmaxf(tmhi, sc[nb][3]);
            }
        }
        tmlo = fmaxf(tmlo, __shfl_xor_sync(0xffffffffu, tmlo, 1));
        tmlo = fmaxf(tmlo, __shfl_xor_sync(0xffffffffu, tmlo, 2));
        tmhi = fmaxf(tmhi, __shfl_xor_sync(0xffffffffu, tmhi, 1));
        tmhi = fmaxf(tmhi, __shfl_xor_sync(0xffffffffu, tmhi, 2));

        float mn_lo = fmaxf(m_lo, tmlo);
        float mn_hi = fmaxf(m_hi, tmhi);
        float alpha_lo = exp2f(m_lo - mn_lo);
        float alpha_hi = exp2f(m_hi - mn_hi);
        m_lo = mn_lo; m_hi = mn_hi;
        #pragma unroll
        for (int nb = 0; nb < 16; nb++) {
            oc[nb][0] *= alpha_lo; oc[nb][1] *= alpha_lo;
            oc[nb][2] *= alpha_hi; oc[nb][3] *= alpha_hi;
        }

        // ---- PV loop with interleaved exp2/split (overlaps MUFU with HMMA) ----
        float slo = 0.f, shi = 0.f;
        #pragma unroll
        for (int ks2 = 0; ks2 < 4; ks2++) {
            uint32_t pah[4], pal[4];
            #pragma unroll
            for (int half = 0; half < 2; half++) {
                const int nb = 2*ks2 + half;
                float p0 = exp2f(sc[nb][0] - mn_lo);
                float p1 = exp2f(sc[nb][1] - mn_lo);
                float p2 = exp2f(sc[nb][2] - mn_hi);
                float p3 = exp2f(sc[nb][3] - mn_hi);
                if (masked) {
                    int c0 = cb + nb*8, c1 = c0 + 1;
                    if (c0 > row_lo) p0 = 0.f;
                    if (c1 > row_lo) p1 = 0.f;
                    if (c0 > row_hi) p2 = 0.f;
                    if (c1 > row_hi) p3 = 0.f;
                }
                slo += p0 + p1; shi += p2 + p3;
                bf16 h0, l0, h1, l1, h2, l2, h3, l3;
                bf16_split(p0, h0, l0);
                bf16_split(p1, h1, l1);
                bf16_split(p2, h2, l2);
                bf16_split(p3, h3, l3);
                pah[half*2 + 0] = pack2(h0, h1);
                pah[half*2 + 1] = pack2(h2, h3);
                pal[half*2 + 0] = pack2(l0, l1);
                pal[half*2 + 1] = pack2(l2, l3);
            }
            #pragma unroll
            for (int npp = 0; npp < 4; npp++) {
                uint32_t vh0[4], vl0[4], vh1[4], vl1[4];
                uint32_t vo0 = (uint32_t)(((ks2*16 + vrow)*FLD + (2*npp)*16 + vcol8)*2);
                uint32_t vo1 = (uint32_t)(((ks2*16 + vrow)*FLD + (2*npp+1)*16 + vcol8)*2);
                ldsm_x4t(vh0, sVh + vo0);
                ldsm_x4t(vl0, sVl + vo0);
                ldsm_x4t(vh1, sVh + vo1);
                ldsm_x4t(vl1, sVl + vo1);
                float* o0 = oc[4*npp + 0];
                float* o1 = oc[4*npp + 1];
                float* o2 = oc[4*npp + 2];
                float* o3 = oc[4*npp + 3];
                mma16816(o0, pal, &vh0[0]);
                mma16816(o1, pal, &vh0[2]);
                mma16816(o2, pal, &vh1[0]);
                mma16816(o3, pal, &vh1[2]);
                mma16816(o0, pah, &vl0[0]);
                mma16816(o1, pah, &vl0[2]);
                mma16816(o2, pah, &vl1[0]);
                mma16816(o3, pah, &vl1[2]);
                mma16816(o0, pah, &vh0[0]);
                mma16816(o1, pah, &vh0[2]);
                mma16816(o2, pah, &vh1[0]);
                mma16816(o3, pah, &vh1[2]);
            }
        }
        slo += __shfl_xor_sync(0xffffffffu, slo, 1);
        slo += __shfl_xor_sync(0xffffffffu, slo, 2);
        shi += __shfl_xor_sync(0xffffffffu, shi, 1);
        shi += __shfl_xor_sync(0xffffffffu, shi, 2);
        l_lo = l_lo * alpha_lo + slo;
        l_hi = l_hi * alpha_hi + shi;
    }

    {
        float inv_lo = 1.f / l_lo;
        float inv_hi = 1.f / l_hi;
        size_t base_lo = ((size_t)(b*SEQ + row_lo))*QDIM + h*HD;
        size_t base_hi = ((size_t)(b*SEQ + row_hi))*QDIM + h*HD;
        #pragma unroll
        for (int nb = 0; nb < 16; nb++) {
            int n0 = nb*8 + (lane & 3)*2;
            float f0 = oc[nb][0]*inv_lo, f1 = oc[nb][1]*inv_lo;
            float f2 = oc[nb][2]*inv_hi, f3 = oc[nb][3]*inv_hi;
            bf16 h0, l0, h1, l1, h2, l2, h3, l3;
            bf16_split(f0, h0, l0);
            bf16_split(f1, h1, l1);
            bf16_split(f2, h2, l2);
            bf16_split(f3, h3, l3);
            *(uint32_t*)&g_Ah[base_lo + n0] = pack2(h0, h1);
            *(uint32_t*)&g_Al[base_lo + n0] = pack2(l0, l1);
            *(uint32_t*)&g_Ah[base_hi + n0] = pack2(h2, h3);
            *(uint32_t*)&g_Al[base_hi + n0] = pack2(l2, l3);
        }
    }
}

// ---------------------------------------------------------------------------
// launch
// ---------------------------------------------------------------------------
extern "C" void kernel_launch(void* const* d_in, const int* in_sizes, int n_in,
                              void* d_out, int out_size)
{
    (void)in_sizes; (void)n_in; (void)out_size;
    const float* hs   = (const float*)d_in[0];
    const float* cosp = (const float*)d_in[1];
    const float* sinp = (const float*)d_in[2];
    const float* Wq   = (const float*)d_in[3];
    const float* bq   = (const float*)d_in[4];
    const float* Wk   = (const float*)d_in[5];
    const float* bk   = (const float*)d_in[6];
    const float* Wv   = (const float*)d_in[7];
    const float* bv   = (const float*)d_in[8];
    const float* Wo   = (const float*)d_in[9];
    float* out = (float*)d_out;

    bf16 *hsh, *hsl, *Wch, *Wcl, *Woh, *Wol, *Ah, *Al;
    cudaGetSymbolAddress((void**)&hsh, g_hsh);
    cudaGetSymbolAddress((void**)&hsl, g_hsl);
    cudaGetSymbolAddress((void**)&Wch, g_Wch);
    cudaGetSymbolAddress((void**)&Wcl, g_Wcl);
    cudaGetSymbolAddress((void**)&Woh, g_Woh);
    cudaGetSymbolAddress((void**)&Wol, g_Wol);
    cudaGetSymbolAddress((void**)&Ah,  g_Ah);
    cudaGetSymbolAddress((void**)&Al,  g_Al);

    cudaFuncSetAttribute(gemm_qkv,
                         cudaFuncAttributeMaxDynamicSharedMemorySize,
                         SMEM3_BYTES);
    cudaFuncSetAttribute(gemm_o,
                         cudaFuncAttributeMaxDynamicSharedMemorySize,
                         SMEM3_BYTES);
    cudaFuncSetAttribute(attn_fa2,
                         cudaFuncAttributeMaxDynamicSharedMemorySize,
                         FATTN_SMEM);

    split_all<<<SP_GRID, 256>>>((const float4*)hs, (const float4*)Wq,
                                (const float4*)Wk, (const float4*)Wv,
                                (const float4*)Wo);

    gemm_qkv<<<dim3(NDIMC/BN3, M_TOK/BM3), 256, SMEM3_BYTES>>>(
        hsh, hsl, Wch, Wcl, bq, bk, bv, cosp, sinp);
    attn_fa2<<<dim3(NQT, NH, BATCH), 256, FATTN_SMEM>>>();
    gemm_o<<<dim3(QDIM/BN3, M_TOK/BM3), 256, SMEM3_BYTES>>>(
        Ah, Al, Woh, Wol, out);
}